// round 13
// baseline (speedup 1.0000x reference)
#include <cuda_runtime.h>
#include <stdint.h>

// Stable counting sort by tile_id (<=256 bins), direct-to-output:
//  k_hist : per-block 256-bin histogram (float4 loads, shared atomics)
//  k_scan : per-bin exclusive scan across blocks (uint4 rows, shuffle scan)
//  k_sort : CHUNK=2048 (dynamic smem, 2 CTA/SM) - recomputes tile id from pos;
//           stable warp ranks in registers; chunk staged LOCALLY SORTED as two
//           float4 shared planes; packed u64 shuffle-scan gives local starts AND
//           tile_offsets; run-coalesced flat flush straight to out.

#define NBIN    256
#define BLK     256
#define NW      8
#define ROUNDS  8
#define WSEG    (ROUNDS * 32)                     // 256 pts per warp
#define CHUNK   (NW * WSEG)                       // 2048 pts per block
#define MAXN    2000000
#define HSTRIDE 2048                              // padded row stride (16B aligned)

// dynamic smem layout for k_sort
#define SMEM_SORT (CHUNK * 16 * 2 + CHUNK * 4 + NW * 8 + NW * NBIN * 2 + NBIN * 4 + NBIN * 2)

__device__ unsigned int  g_histB[NBIN * HSTRIDE];
__device__ unsigned int  g_baseB[NBIN * HSTRIDE];
__device__ unsigned int  g_counts[NBIN];

// ---------------- per-block histogram (vectorized, shared atomics) ----------------
__global__ void __launch_bounds__(BLK) k_hist(const float4* __restrict__ pos4,
                                              const int* __restrict__ pnum,
                                              int N) {
    __shared__ unsigned int cnt[NBIN];
    int tid = threadIdx.x;
    cnt[tid] = 0u;
    __syncthreads();
    int nt = *pnum;
    float inv_ts = (float)nt / 1024.0f;     // exact for power-of-two tile size
    int base4 = blockIdx.x * (CHUNK / 2);
    #pragma unroll
    for (int r = 0; r < CHUNK / 2 / BLK; r++) {   // 4 rounds, 2 pts each
        int i4 = base4 + r * BLK + tid;
        int p0 = 2 * i4;
        if (p0 + 1 < N) {
            float4 v = pos4[i4];
            int tx0 = min(max((int)(v.x * inv_ts), 0), nt - 1);
            int ty0 = min(max((int)(v.y * inv_ts), 0), nt - 1);
            int tx1 = min(max((int)(v.z * inv_ts), 0), nt - 1);
            int ty1 = min(max((int)(v.w * inv_ts), 0), nt - 1);
            atomicAdd(&cnt[ty0 * nt + tx0], 1u);
            atomicAdd(&cnt[ty1 * nt + tx1], 1u);
        } else if (p0 < N) {
            float2 v = ((const float2*)pos4)[2 * i4];
            int tx0 = min(max((int)(v.x * inv_ts), 0), nt - 1);
            int ty0 = min(max((int)(v.y * inv_ts), 0), nt - 1);
            atomicAdd(&cnt[ty0 * nt + tx0], 1u);
        }
    }
    __syncthreads();
    g_histB[tid * HSTRIDE + blockIdx.x] = cnt[tid];
}

// -------- per-bin exclusive scan across blocks (uint4 rows, shuffle scan) --------
__global__ void __launch_bounds__(BLK) k_scan(const int* __restrict__ pnum,
                                              int N, int nblk,
                                              float* __restrict__ out) {
    int bin = blockIdx.x;
    int tid = threadIdx.x;
    int lane = tid & 31;
    int warp = tid >> 5;
    unsigned base = (unsigned)bin * HSTRIDE + tid * 8u;
    uint4 A = *(const uint4*)&g_histB[base];
    uint4 B = *(const uint4*)&g_histB[base + 4];
    unsigned v[8] = {A.x, A.y, A.z, A.w, B.x, B.y, B.z, B.w};
    unsigned s = 0;
    #pragma unroll
    for (int j = 0; j < 8; j++) {
        if ((int)(tid * 8 + j) >= nblk) v[j] = 0u;
        s += v[j];
    }
    __shared__ unsigned wsum[NW];
    unsigned x = s;
    #pragma unroll
    for (int d = 1; d < 32; d <<= 1) {
        unsigned y = __shfl_up_sync(0xffffffffu, x, d);
        if (lane >= d) x += y;
    }
    if (lane == 31) wsum[warp] = x;
    __syncthreads();
    if (warp == 0) {
        unsigned t = (lane < NW) ? wsum[lane] : 0u;
        #pragma unroll
        for (int d = 1; d < NW; d <<= 1) {
            unsigned y = __shfl_up_sync(0xffffffffu, t, d);
            if (lane >= d) t += y;
        }
        if (lane < NW) wsum[lane] = t;
    }
    __syncthreads();
    unsigned incl = x + (warp ? wsum[warp - 1] : 0u);
    unsigned run = incl - s;                       // exclusive
    unsigned o[8];
    #pragma unroll
    for (int j = 0; j < 8; j++) { o[j] = run; run += v[j]; }
    *(uint4*)&g_baseB[base]     = make_uint4(o[0], o[1], o[2], o[3]);
    *(uint4*)&g_baseB[base + 4] = make_uint4(o[4], o[5], o[6], o[7]);
    if (tid == BLK - 1) {
        g_counts[bin] = incl;
        int nt2 = (*pnum) * (*pnum);
        if (bin < nt2)
            out[7ull * (unsigned long long)N + bin] = (float)incl;
    }
}

// ------- rank + feature math + float4-plane staging + run-coalesced output -------
__global__ void __launch_bounds__(BLK) k_sort(
    const float2* __restrict__ pos, const float4* __restrict__ cov,
    const float* __restrict__ opac, const int* __restrict__ pnum,
    int N, float* __restrict__ out)
{
    extern __shared__ char smembuf[];
    float4*             pA   = (float4*)smembuf;                 // CHUNK feats 0-3
    float4*             pB   = pA + CHUNK;                       // CHUNK feats 4-6 + p
    unsigned*           gdst = (unsigned*)(pB + CHUNK);          // CHUNK
    unsigned long long* wsum = (unsigned long long*)(gdst + CHUNK);
    unsigned short*     wcnt = (unsigned short*)(wsum + NW);     // NW*NBIN
    int*                adj  = (int*)(wcnt + NW * NBIN);         // NBIN
    unsigned short*     sbinstart = (unsigned short*)(adj + NBIN);

    int tid  = threadIdx.x;
    int lane = tid & 31;
    int warp = tid >> 5;
    unsigned lt = (1u << lane) - 1u;
    int blk = blockIdx.x;
    int chunkStart = blk * CHUNK;
    int valid = min(CHUNK, N - chunkStart);
    int nt = *pnum;
    int nt2 = nt * nt;
    float inv_ts = (float)nt / 1024.0f;

    #pragma unroll
    for (int i = 0; i < NW * NBIN / 2 / BLK; i++)
        ((uint32_t*)wcnt)[i * BLK + tid] = 0u;
    __syncthreads();

    // Phase A: tile id from pos (kept in regs), stable within-warp ranks
    unsigned short* mycnt = &wcnt[warp * NBIN];
    unsigned packed[ROUNDS];
    float2 xy[ROUNDS];
    #pragma unroll
    for (int r = 0; r < ROUNDS; r++) {
        int local = warp * WSEG + r * 32 + lane;
        int p = chunkStart + local;
        int k = 300;
        if (p < N) {
            xy[r] = pos[p];
            int tx = min(max((int)(xy[r].x * inv_ts), 0), nt - 1);
            int ty = min(max((int)(xy[r].y * inv_ts), 0), nt - 1);
            k = ty * nt + tx;
        }
        unsigned mask = __match_any_sync(0xffffffffu, k);
        int leader = __ffs(mask) - 1;
        int rank_w = __popc(mask & lt);
        unsigned base = 0u;
        if (lane == leader && k < 256) {
            base = (unsigned)mycnt[k];
            mycnt[k] = (unsigned short)(base + (unsigned)__popc(mask));
        }
        base = __shfl_sync(0xffffffffu, base, leader);
        packed[r] = ((base + (unsigned)rank_w) << 16) | (unsigned)(k & 0xffff);
    }
    __syncthreads();

    // Combine: warp prefix per bin; packed u64 shuffle-scan:
    //   lo = exscan(g_counts) = tile_offsets, hi = exscan(local totals) = starts.
    unsigned loc;
    {
        unsigned s = 0u;
        #pragma unroll
        for (int w = 0; w < NW; w++) {
            unsigned c = (unsigned)wcnt[w * NBIN + tid];
            wcnt[w * NBIN + tid] = (unsigned short)s;
            s += c;
        }
        loc = s;
    }
    unsigned cntg = g_counts[tid];
    unsigned long long v64 = ((unsigned long long)loc << 32) | (unsigned long long)cntg;
    unsigned long long x = v64;
    #pragma unroll
    for (int d = 1; d < 32; d <<= 1) {
        unsigned long long y = __shfl_up_sync(0xffffffffu, x, d);
        if (lane >= d) x += y;
    }
    if (lane == 31) wsum[warp] = x;
    __syncthreads();
    if (warp == 0) {
        unsigned long long t = (lane < NW) ? wsum[lane] : 0ull;
        #pragma unroll
        for (int d = 1; d < NW; d <<= 1) {
            unsigned long long y = __shfl_up_sync(0xffffffffu, t, d);
            if (lane >= d) t += y;
        }
        if (lane < NW) wsum[lane] = t;
    }
    __syncthreads();
    {
        unsigned long long incl = x + (warp ? wsum[warp - 1] : 0ull);
        unsigned long long excl = incl - v64;
        unsigned offs = (unsigned)excl;
        unsigned bs   = (unsigned)(excl >> 32);
        sbinstart[tid] = (unsigned short)bs;
        adj[tid] = (int)(offs + g_baseB[tid * HSTRIDE + blk]) - (int)bs;
        if (blk == 0 && tid < nt2)
            out[7ull * (unsigned long long)N + nt2 + tid] = (float)offs;
    }
    __syncthreads();

    // Phase C: cov/opac reads + math -> two STS.128 to locally-sorted slot
    #pragma unroll
    for (int r = 0; r < ROUNDS; r++) {
        int local = warp * WSEG + r * 32 + lane;
        int p = chunkStart + local;
        if (p < N) {
            int k = (int)(packed[r] & 0xffffu);
            int slot = (int)sbinstart[k] + (int)wcnt[warp * NBIN + k]
                     + (int)(packed[r] >> 16);

            float4 cv = cov[p];
            float op  = opac[p];
            float a = cv.x, b = cv.y, c = cv.z, d = cv.w;
            float trace = a + d;
            float det   = a * d - b * c;
            float t1 = 0.5f * trace;
            float disc = trace * trace - 4.0f * det;
            float t2 = 0.5f * sqrtf(fmaxf(disc, 0.0f));
            float radius = fmaxf(t1 - t2, t1 + t2);
            float inv = 1.0f / det;

            pA[slot] = make_float4(xy[r].x, xy[r].y, d * inv, -b * inv);
            pB[slot] = make_float4(a * inv, op, radius, (float)p);
            gdst[slot] = (unsigned)(adj[k] + slot);
        }
    }
    __syncthreads();

    // Flush: run-coalesced flat copies from the two planes.
    unsigned long long orderBase =
        7ull * (unsigned long long)N + 2ull * (unsigned long long)nt2;
    const float* fA = (const float*)pA;
    const float* fB = (const float*)pB;
    if (valid == CHUNK) {
        int c = tid % 7;
        int j = tid / 7;
        #pragma unroll
        for (int r = 0; r < CHUNK * 7 / BLK; r++) {       // 56 iterations
            float val = (c < 4) ? fA[4 * j + c] : fB[4 * j + c - 4];
            out[gdst[j] * 7u + (unsigned)c] = val;
            int cn = c + 4;                               // 256 = 7*36 + 4
            bool wrap = (cn >= 7);
            c = wrap ? cn - 7 : cn;
            j += wrap ? 37 : 36;
        }
        #pragma unroll
        for (int r = 0; r < CHUNK / BLK; r++) {
            int i = r * BLK + tid;
            out[orderBase + gdst[i]] = fB[4 * i + 3];
        }
    } else {
        int totF = valid * 7;
        for (int i = tid; i < totF; i += BLK) {
            int j = i / 7;
            int c = i - 7 * j;
            float val = (c < 4) ? fA[4 * j + c] : fB[4 * j + c - 4];
            out[gdst[j] * 7u + (unsigned)c] = val;
        }
        for (int i = tid; i < valid; i += BLK)
            out[orderBase + gdst[i]] = fB[4 * i + 3];
    }
}

extern "C" void kernel_launch(void* const* d_in, const int* in_sizes, int n_in,
                              void* d_out, int out_size) {
    const float4* pos4 = (const float4*)d_in[0];
    const float2* pos  = (const float2*)d_in[0];
    const float4* cov  = (const float4*)d_in[1];
    const float*  op   = (const float*)d_in[2];
    const int*    pnum = (const int*)d_in[3];
    int N = in_sizes[0] / 2;
    int nblk = (N + CHUNK - 1) / CHUNK;
    float* out = (float*)d_out;

    cudaFuncSetAttribute(k_sort, cudaFuncAttributeMaxDynamicSharedMemorySize,
                         SMEM_SORT);

    k_hist<<<nblk, BLK>>>(pos4, pnum, N);
    k_scan<<<NBIN, BLK>>>(pnum, N, nblk, out);
    k_sort<<<nblk, BLK, SMEM_SORT>>>(pos, cov, op, pnum, N, out);
}

// round 14
// speedup vs baseline: 1.2558x; 1.2558x over previous
#include <cuda_runtime.h>
#include <stdint.h>

// Stable counting sort by tile_id (<=256 bins), direct-to-output:
//  k_hist : 2048-pt blocks emitting TWO 1024-pt sub-histogram columns
//           (float4 loads, split shared atomics)
//  k_scan : per-bin exclusive scan across blocks (uint4 rows, shuffle scan)
//  k_sort : 1024-pt blocks (static 44KB smem, 4 CTA/SM) - recomputes tile id;
//           stable warp ranks in registers; chunk staged LOCALLY SORTED as two
//           float4 shared planes; packed u64 shuffle-scan gives local starts AND
//           tile_offsets; run-coalesced flat flush straight to out.

#define NBIN    256
#define BLK     256
#define NW      8
#define ROUNDS  4
#define WSEG    (ROUNDS * 32)                     // 128 pts per warp
#define CHUNK   (NW * WSEG)                       // 1024 pts per sort block
#define HCHUNK  (2 * CHUNK)                       // 2048 pts per hist block
#define MAXN    2000000
#define HSTRIDE 2048                              // padded row stride (16B aligned)

__device__ unsigned int  g_histB[NBIN * HSTRIDE];
__device__ unsigned int  g_baseB[NBIN * HSTRIDE];
__device__ unsigned int  g_counts[NBIN];

// ------- per-block histogram: 2048 pts, two 1024-pt sub-columns -------
__global__ void __launch_bounds__(BLK) k_hist(const float4* __restrict__ pos4,
                                              const int* __restrict__ pnum,
                                              int N) {
    __shared__ unsigned int cnt[2][NBIN];
    int tid = threadIdx.x;
    cnt[0][tid] = 0u;
    cnt[1][tid] = 0u;
    __syncthreads();
    int nt = *pnum;
    float inv_ts = (float)nt / 1024.0f;     // exact for power-of-two tile size
    int base4 = blockIdx.x * (HCHUNK / 2);
    #pragma unroll
    for (int r = 0; r < HCHUNK / 2 / BLK; r++) {  // 4 rounds, 2 pts each
        int i4 = base4 + r * BLK + tid;
        int p0 = 2 * i4;
        int half = r >> 1;                        // rounds 0,1 -> sub 0; 2,3 -> sub 1
        if (p0 + 1 < N) {
            float4 v = pos4[i4];
            int tx0 = min(max((int)(v.x * inv_ts), 0), nt - 1);
            int ty0 = min(max((int)(v.y * inv_ts), 0), nt - 1);
            int tx1 = min(max((int)(v.z * inv_ts), 0), nt - 1);
            int ty1 = min(max((int)(v.w * inv_ts), 0), nt - 1);
            atomicAdd(&cnt[half][ty0 * nt + tx0], 1u);
            atomicAdd(&cnt[half][ty1 * nt + tx1], 1u);
        } else if (p0 < N) {
            float2 v = ((const float2*)pos4)[2 * i4];
            int tx0 = min(max((int)(v.x * inv_ts), 0), nt - 1);
            int ty0 = min(max((int)(v.y * inv_ts), 0), nt - 1);
            atomicAdd(&cnt[half][ty0 * nt + tx0], 1u);
        }
    }
    __syncthreads();
    g_histB[tid * HSTRIDE + 2 * blockIdx.x]     = cnt[0][tid];
    g_histB[tid * HSTRIDE + 2 * blockIdx.x + 1] = cnt[1][tid];
}

// -------- per-bin exclusive scan across blocks (uint4 rows, shuffle scan) --------
__global__ void __launch_bounds__(BLK) k_scan(const int* __restrict__ pnum,
                                              int N, int nblk,
                                              float* __restrict__ out) {
    int bin = blockIdx.x;
    int tid = threadIdx.x;
    int lane = tid & 31;
    int warp = tid >> 5;
    unsigned base = (unsigned)bin * HSTRIDE + tid * 8u;
    uint4 A = *(const uint4*)&g_histB[base];
    uint4 B = *(const uint4*)&g_histB[base + 4];
    unsigned v[8] = {A.x, A.y, A.z, A.w, B.x, B.y, B.z, B.w};
    unsigned s = 0;
    #pragma unroll
    for (int j = 0; j < 8; j++) {
        if ((int)(tid * 8 + j) >= nblk) v[j] = 0u;
        s += v[j];
    }
    __shared__ unsigned wsum[NW];
    unsigned x = s;
    #pragma unroll
    for (int d = 1; d < 32; d <<= 1) {
        unsigned y = __shfl_up_sync(0xffffffffu, x, d);
        if (lane >= d) x += y;
    }
    if (lane == 31) wsum[warp] = x;
    __syncthreads();
    if (warp == 0) {
        unsigned t = (lane < NW) ? wsum[lane] : 0u;
        #pragma unroll
        for (int d = 1; d < NW; d <<= 1) {
            unsigned y = __shfl_up_sync(0xffffffffu, t, d);
            if (lane >= d) t += y;
        }
        if (lane < NW) wsum[lane] = t;
    }
    __syncthreads();
    unsigned incl = x + (warp ? wsum[warp - 1] : 0u);
    unsigned run = incl - s;                       // exclusive
    unsigned o[8];
    #pragma unroll
    for (int j = 0; j < 8; j++) { o[j] = run; run += v[j]; }
    *(uint4*)&g_baseB[base]     = make_uint4(o[0], o[1], o[2], o[3]);
    *(uint4*)&g_baseB[base + 4] = make_uint4(o[4], o[5], o[6], o[7]);
    if (tid == BLK - 1) {
        g_counts[bin] = incl;
        int nt2 = (*pnum) * (*pnum);
        if (bin < nt2)
            out[7ull * (unsigned long long)N + bin] = (float)incl;
    }
}

// ------- rank + feature math + float4-plane staging + run-coalesced output -------
__global__ void __launch_bounds__(BLK) k_sort(
    const float2* __restrict__ pos, const float4* __restrict__ cov,
    const float* __restrict__ opac, const int* __restrict__ pnum,
    int N, float* __restrict__ out)
{
    __shared__ float4         pA[CHUNK];            // 16KB feats 0-3 per slot
    __shared__ float4         pB[CHUNK];            // 16KB feats 4-6 + p per slot
    __shared__ unsigned int   gdst[CHUNK];          // 4KB global record idx per slot
    __shared__ unsigned short wcnt[NW * NBIN];      // 4KB counters -> warp prefix
    __shared__ unsigned short sbinstart[NBIN];
    __shared__ int            adj[NBIN];
    __shared__ unsigned long long wsum[NW];

    int tid  = threadIdx.x;
    int lane = tid & 31;
    int warp = tid >> 5;
    unsigned lt = (1u << lane) - 1u;
    int blk = blockIdx.x;
    int chunkStart = blk * CHUNK;
    int valid = min(CHUNK, N - chunkStart);
    int nt = *pnum;
    int nt2 = nt * nt;
    float inv_ts = (float)nt / 1024.0f;

    #pragma unroll
    for (int i = 0; i < NW * NBIN / 2 / BLK; i++)
        ((uint32_t*)wcnt)[i * BLK + tid] = 0u;
    __syncthreads();

    // Phase A: tile id from pos (kept in regs), stable within-warp ranks
    unsigned short* mycnt = &wcnt[warp * NBIN];
    unsigned packed[ROUNDS];
    float2 xy[ROUNDS];
    #pragma unroll
    for (int r = 0; r < ROUNDS; r++) {
        int local = warp * WSEG + r * 32 + lane;
        int p = chunkStart + local;
        int k = 300;
        if (p < N) {
            xy[r] = pos[p];
            int tx = min(max((int)(xy[r].x * inv_ts), 0), nt - 1);
            int ty = min(max((int)(xy[r].y * inv_ts), 0), nt - 1);
            k = ty * nt + tx;
        }
        unsigned mask = __match_any_sync(0xffffffffu, k);
        int leader = __ffs(mask) - 1;
        int rank_w = __popc(mask & lt);
        unsigned base = 0u;
        if (lane == leader && k < 256) {
            base = (unsigned)mycnt[k];
            mycnt[k] = (unsigned short)(base + (unsigned)__popc(mask));
        }
        base = __shfl_sync(0xffffffffu, base, leader);
        packed[r] = ((base + (unsigned)rank_w) << 16) | (unsigned)(k & 0xffff);
    }
    __syncthreads();

    // Combine: warp prefix per bin; packed u64 shuffle-scan:
    //   lo = exscan(g_counts) = tile_offsets, hi = exscan(local totals) = starts.
    unsigned loc;
    {
        unsigned s = 0u;
        #pragma unroll
        for (int w = 0; w < NW; w++) {
            unsigned c = (unsigned)wcnt[w * NBIN + tid];
            wcnt[w * NBIN + tid] = (unsigned short)s;
            s += c;
        }
        loc = s;
    }
    unsigned cntg = g_counts[tid];
    unsigned long long v64 = ((unsigned long long)loc << 32) | (unsigned long long)cntg;
    unsigned long long x = v64;
    #pragma unroll
    for (int d = 1; d < 32; d <<= 1) {
        unsigned long long y = __shfl_up_sync(0xffffffffu, x, d);
        if (lane >= d) x += y;
    }
    if (lane == 31) wsum[warp] = x;
    __syncthreads();
    if (warp == 0) {
        unsigned long long t = (lane < NW) ? wsum[lane] : 0ull;
        #pragma unroll
        for (int d = 1; d < NW; d <<= 1) {
            unsigned long long y = __shfl_up_sync(0xffffffffu, t, d);
            if (lane >= d) t += y;
        }
        if (lane < NW) wsum[lane] = t;
    }
    __syncthreads();
    {
        unsigned long long incl = x + (warp ? wsum[warp - 1] : 0ull);
        unsigned long long excl = incl - v64;
        unsigned offs = (unsigned)excl;
        unsigned bs   = (unsigned)(excl >> 32);
        sbinstart[tid] = (unsigned short)bs;
        adj[tid] = (int)(offs + g_baseB[tid * HSTRIDE + blk]) - (int)bs;
        if (blk == 0 && tid < nt2)
            out[7ull * (unsigned long long)N + nt2 + tid] = (float)offs;
    }
    __syncthreads();

    // Phase C: cov/opac reads + math -> two STS.128 to locally-sorted slot
    #pragma unroll
    for (int r = 0; r < ROUNDS; r++) {
        int local = warp * WSEG + r * 32 + lane;
        int p = chunkStart + local;
        if (p < N) {
            int k = (int)(packed[r] & 0xffffu);
            int slot = (int)sbinstart[k] + (int)mycnt[k] + (int)(packed[r] >> 16);

            float4 cv = cov[p];
            float op  = opac[p];
            float a = cv.x, b = cv.y, c = cv.z, d = cv.w;
            float trace = a + d;
            float det   = a * d - b * c;
            float t1 = 0.5f * trace;
            float disc = trace * trace - 4.0f * det;
            float t2 = 0.5f * sqrtf(fmaxf(disc, 0.0f));
            float radius = fmaxf(t1 - t2, t1 + t2);
            float inv = 1.0f / det;

            pA[slot] = make_float4(xy[r].x, xy[r].y, d * inv, -b * inv);
            pB[slot] = make_float4(a * inv, op, radius, (float)p);
            gdst[slot] = (unsigned)(adj[k] + slot);
        }
    }
    __syncthreads();

    // Flush: run-coalesced flat copies from the two planes.
    unsigned long long orderBase =
        7ull * (unsigned long long)N + 2ull * (unsigned long long)nt2;
    const float* fA = (const float*)pA;
    const float* fB = (const float*)pB;
    if (valid == CHUNK) {
        int c = tid % 7;
        int j = tid / 7;
        #pragma unroll
        for (int r = 0; r < CHUNK * 7 / BLK; r++) {       // 28 iterations
            float val = (c < 4) ? fA[4 * j + c] : fB[4 * j + c - 4];
            out[gdst[j] * 7u + (unsigned)c] = val;
            int cn = c + 4;                               // 256 = 7*36 + 4
            bool wrap = (cn >= 7);
            c = wrap ? cn - 7 : cn;
            j += wrap ? 37 : 36;
        }
        #pragma unroll
        for (int r = 0; r < CHUNK / BLK; r++) {
            int i = r * BLK + tid;
            out[orderBase + gdst[i]] = fB[4 * i + 3];
        }
    } else {
        int totF = valid * 7;
        for (int i = tid; i < totF; i += BLK) {
            int j = i / 7;
            int c = i - 7 * j;
            float val = (c < 4) ? fA[4 * j + c] : fB[4 * j + c - 4];
            out[gdst[j] * 7u + (unsigned)c] = val;
        }
        for (int i = tid; i < valid; i += BLK)
            out[orderBase + gdst[i]] = fB[4 * i + 3];
    }
}

extern "C" void kernel_launch(void* const* d_in, const int* in_sizes, int n_in,
                              void* d_out, int out_size) {
    const float4* pos4 = (const float4*)d_in[0];
    const float2* pos  = (const float2*)d_in[0];
    const float4* cov  = (const float4*)d_in[1];
    const float*  op   = (const float*)d_in[2];
    const int*    pnum = (const int*)d_in[3];
    int N = in_sizes[0] / 2;
    int nblk  = (N + CHUNK - 1) / CHUNK;     // k_sort/scan granularity (1024)
    int hblk  = (N + HCHUNK - 1) / HCHUNK;   // k_hist granularity (2048)
    float* out = (float*)d_out;

    k_hist<<<hblk, BLK>>>(pos4, pnum, N);
    k_scan<<<NBIN, BLK>>>(pnum, N, nblk, out);
    k_sort<<<nblk, BLK>>>(pos, cov, op, pnum, N, out);
}